// round 1
// baseline (speedup 1.0000x reference)
#include <cuda_runtime.h>

// Attention_18021682774359: BiDAF-style context-query attention.
// B=64, CL=400, QL=50, H=1024. Output [B, CL, 4H] fp32.
//
// Pipeline:
//  K0a  cdot[b,i] = c_i . c_weight ; qdot[b,j] = q_j . q_weight
//  K0b  qpad[b,j,h] = q (rows 50..63 zero)
//  K1   G[b,i,j]  = sum_h (c[b,i,h]*cqw[h]) * qpad[b,j,h]   (tiled GEMM)
//  K2a  s1 = softmax_j(G + cdot + qdot + bias, q_mask)  (+ zero-pad s1/s2 cols)
//  K2b  s2 = softmax_i(G + cdot + qdot + bias, c_mask)
//  K3   t[b,j,h]  = sum_i s2[b,i,j] * c[b,i,h]              (tiled GEMM)
//  K4   a = s1 @ qpad ; bb = s1 @ t ; out = [c, a, c*a, c*bb]

namespace {
constexpr int B_  = 64;
constexpr int CL_ = 400;
constexpr int QL_ = 50;
constexpr int H_  = 1024;
constexpr int QS_ = 64;   // padded QL
}

// -------- scratch (device globals; allocation-free) --------
__device__ float g_G   [B_*CL_*QS_];   // raw similarity GEMM part
__device__ float g_s1  [B_*CL_*QS_];   // softmax over q (cols 50..63 zero)
__device__ float g_s2  [B_*CL_*QS_];   // softmax over c (cols 50..63 zero)
__device__ float g_qpad[B_*QS_*H_];    // q zero-padded to 64 rows per batch
__device__ float g_t   [B_*QS_*H_];    // s2^T @ c, padded rows are zero
__device__ float g_cdot[B_*CL_];
__device__ float g_qdot[B_*QS_];

// ============================================================
// K0a: row dot products with weight vectors (warp per row)
// ============================================================
__global__ __launch_bounds__(256) void k_dots(
    const float* __restrict__ c, const float* __restrict__ q,
    const float* __restrict__ cw, const float* __restrict__ qw)
{
    int gw   = (blockIdx.x * blockDim.x + threadIdx.x) >> 5;
    int lane = threadIdx.x & 31;
    const int NC = B_ * CL_;
    if (gw >= NC + B_ * QL_) return;

    const float4* row;
    const float4* w;
    if (gw < NC) { row = (const float4*)c + gw * (H_/4);        w = (const float4*)cw; }
    else         { row = (const float4*)q + (gw - NC) * (H_/4); w = (const float4*)qw; }

    float s = 0.f;
#pragma unroll
    for (int r = 0; r < 8; r++) {
        float4 a = row[lane + 32*r];
        float4 b = w  [lane + 32*r];
        s += a.x*b.x + a.y*b.y + a.z*b.z + a.w*b.w;
    }
#pragma unroll
    for (int o = 16; o; o >>= 1) s += __shfl_xor_sync(0xffffffffu, s, o);
    if (lane == 0) {
        if (gw < NC) g_cdot[gw] = s;
        else { int r = gw - NC; g_qdot[(r / QL_) * QS_ + (r % QL_)] = s; }
    }
}

// ============================================================
// K0b: build zero-padded q copy [B,64,H]
// ============================================================
__global__ __launch_bounds__(256) void k_qpad(const float* __restrict__ q)
{
    int idx = blockIdx.x * blockDim.x + threadIdx.x;   // float4 index
    int h4 = idx & 255;
    int j  = (idx >> 8) & 63;
    int b  = idx >> 14;
    float4 v = make_float4(0.f, 0.f, 0.f, 0.f);
    if (j < QL_) v = ((const float4*)q)[((b * QL_ + j) << 8) + h4];
    ((float4*)g_qpad)[idx] = v;
}

// ============================================================
// K1: G = (c . cqw) @ qpad^T  per batch. Tile 64x64, K-chunks 32.
// Block 128 threads (8 tx x 16 ty), micro-tile 4(m) x 8(n).
// ============================================================
__global__ __launch_bounds__(128) void k_simgemm(
    const float* __restrict__ c, const float* __restrict__ cqw)
{
    __shared__ __align__(16) float As[32][68];   // As[k][m]  (c * cqw, transposed)
    __shared__ __align__(16) float Bs[32][68];   // Bs[k][j]  (qpad, transposed)

    int b  = blockIdx.y;
    int i0 = blockIdx.x * 64;
    int tid = threadIdx.x;
    int tx = tid & 7, ty = tid >> 3;

    const float* cb = c      + (size_t)b * CL_ * H_;
    const float* qb = g_qpad + (size_t)b * QS_ * H_;

    float acc[4][8];
#pragma unroll
    for (int i = 0; i < 4; i++)
#pragma unroll
        for (int j = 0; j < 8; j++) acc[i][j] = 0.f;

    for (int kc = 0; kc < H_; kc += 32) {
#pragma unroll
        for (int r = 0; r < 4; r++) {
            int p  = tid + 128 * r;         // 512 float4 per tile
            int m  = p >> 3;
            int k4 = (p & 7) * 4;
            // A: c row i0+m, scaled by cqw, store transposed
            float4 v = make_float4(0.f, 0.f, 0.f, 0.f);
            int gi = i0 + m;
            if (gi < CL_) {
                v = *(const float4*)(cb + gi * H_ + kc + k4);
                float4 w = *(const float4*)(cqw + kc + k4);
                v.x *= w.x; v.y *= w.y; v.z *= w.z; v.w *= w.w;
            }
            As[k4+0][m] = v.x; As[k4+1][m] = v.y; As[k4+2][m] = v.z; As[k4+3][m] = v.w;
            // B: qpad row m (all 64 rows exist)
            float4 u = *(const float4*)(qb + m * H_ + kc + k4);
            Bs[k4+0][m] = u.x; Bs[k4+1][m] = u.y; Bs[k4+2][m] = u.z; Bs[k4+3][m] = u.w;
        }
        __syncthreads();

#pragma unroll
        for (int kk = 0; kk < 32; kk++) {
            float4 av = *(const float4*)&As[kk][ty*4];
            float4 b0 = *(const float4*)&Bs[kk][tx*8];
            float4 b1 = *(const float4*)&Bs[kk][tx*8 + 4];
            float a_[4] = {av.x, av.y, av.z, av.w};
            float b_[8] = {b0.x,b0.y,b0.z,b0.w, b1.x,b1.y,b1.z,b1.w};
#pragma unroll
            for (int ii = 0; ii < 4; ii++)
#pragma unroll
                for (int jj = 0; jj < 8; jj++) acc[ii][jj] += a_[ii] * b_[jj];
        }
        __syncthreads();
    }

#pragma unroll
    for (int im = 0; im < 4; im++) {
        int gi = i0 + ty*4 + im;
        if (gi < CL_) {
            float* g = g_G + ((b * CL_ + gi) << 6) + tx*8;
            *(float4*)(g)     = make_float4(acc[im][0], acc[im][1], acc[im][2], acc[im][3]);
            *(float4*)(g + 4) = make_float4(acc[im][4], acc[im][5], acc[im][6], acc[im][7]);
        }
    }
}

// ============================================================
// K2a: softmax over q dim (warp per (b,i) row). Also zero-pads s1/s2 cols.
// ============================================================
__global__ __launch_bounds__(256) void k_soft1(
    const int* __restrict__ qmask, const float* __restrict__ bias)
{
    int gw   = (blockIdx.x * 256 + threadIdx.x) >> 5;   // row = b*CL + i
    int lane = threadIdx.x & 31;
    if (gw >= B_ * CL_) return;
    int b = gw / CL_;
    float bi = bias[0];
    float cd = g_cdot[gw];
    const float* Grow = g_G + ((size_t)gw << 6);

    int j1 = lane, j2 = lane + 32;
    float v1 = qmask[b * QL_ + j1] ? (Grow[j1] + cd + g_qdot[b*QS_ + j1] + bi) : -1e30f;
    float v2 = -1e38f;
    if (j2 < QL_) v2 = qmask[b * QL_ + j2] ? (Grow[j2] + cd + g_qdot[b*QS_ + j2] + bi) : -1e30f;

    float mx = fmaxf(v1, v2);
#pragma unroll
    for (int o = 16; o; o >>= 1) mx = fmaxf(mx, __shfl_xor_sync(0xffffffffu, mx, o));
    float e1 = expf(v1 - mx);
    float e2 = (j2 < QL_) ? expf(v2 - mx) : 0.f;
    float s = e1 + e2;
#pragma unroll
    for (int o = 16; o; o >>= 1) s += __shfl_xor_sync(0xffffffffu, s, o);
    float inv = 1.f / s;

    float* s1row = g_s1 + ((size_t)gw << 6);
    s1row[j1] = e1 * inv;
    s1row[j2] = (j2 < QL_) ? e2 * inv : 0.f;
    if (j2 >= QL_) g_s2[((size_t)gw << 6) + j2] = 0.f;  // pad s2 cols 50..63
}

// ============================================================
// K2b: softmax over c dim (warp per (b,j) column)
// ============================================================
__global__ __launch_bounds__(256) void k_soft2(
    const int* __restrict__ cmask, const float* __restrict__ bias)
{
    int gw   = (blockIdx.x * 256 + threadIdx.x) >> 5;   // col = b*QL + j
    int lane = threadIdx.x & 31;
    if (gw >= B_ * QL_) return;
    int b = gw / QL_, j = gw % QL_;
    float qd = g_qdot[b*QS_ + j] + bias[0];

    float v[13];
#pragma unroll
    for (int r = 0; r < 13; r++) {
        int i = lane + 32 * r;
        if (i < CL_) {
            float s = g_G[((size_t)(b * CL_ + i) << 6) + j] + g_cdot[b*CL_ + i] + qd;
            v[r] = cmask[b*CL_ + i] ? s : -1e30f;
        } else v[r] = -1e38f;
    }
    float mx = v[0];
#pragma unroll
    for (int r = 1; r < 13; r++) mx = fmaxf(mx, v[r]);
#pragma unroll
    for (int o = 16; o; o >>= 1) mx = fmaxf(mx, __shfl_xor_sync(0xffffffffu, mx, o));

    float e[13], sum = 0.f;
#pragma unroll
    for (int r = 0; r < 13; r++) {
        int i = lane + 32 * r;
        e[r] = (i < CL_) ? expf(v[r] - mx) : 0.f;
        sum += e[r];
    }
#pragma unroll
    for (int o = 16; o; o >>= 1) sum += __shfl_xor_sync(0xffffffffu, sum, o);
    float inv = 1.f / sum;
#pragma unroll
    for (int r = 0; r < 13; r++) {
        int i = lane + 32 * r;
        if (i < CL_) g_s2[((size_t)(b * CL_ + i) << 6) + j] = e[r] * inv;
    }
}

// ============================================================
// K3: t[b,j,h] = sum_i s2[b,i,j] * c[b,i,h]. Tile 64(j) x 64(h), K=CL chunks 32.
// ============================================================
__global__ __launch_bounds__(128) void k_s2tc(const float* __restrict__ c)
{
    __shared__ __align__(16) float As[32][68];   // As[kk][j] = s2[i0+kk][j]
    __shared__ __align__(16) float Bs[32][68];   // Bs[kk][n] = c [i0+kk][h0+n]

    int b  = blockIdx.y;
    int h0 = blockIdx.x * 64;
    int tid = threadIdx.x;
    int tx = tid & 7, ty = tid >> 3;

    float acc[4][8];
#pragma unroll
    for (int i = 0; i < 4; i++)
#pragma unroll
        for (int j = 0; j < 8; j++) acc[i][j] = 0.f;

    for (int k0 = 0; k0 < CL_; k0 += 32) {
#pragma unroll
        for (int r = 0; r < 4; r++) {
            int p  = tid + 128 * r;
            int kk = p >> 4;
            int x4 = (p & 15) * 4;
            int gi = k0 + kk;
            float4 a = make_float4(0.f,0.f,0.f,0.f), v = a;
            if (gi < CL_) {
                a = *(const float4*)(g_s2 + ((size_t)(b * CL_ + gi) << 6) + x4);
                v = *(const float4*)(c    + (size_t)(b * CL_ + gi) * H_ + h0 + x4);
            }
            *(float4*)&As[kk][x4] = a;
            *(float4*)&Bs[kk][x4] = v;
        }
        __syncthreads();

#pragma unroll
        for (int kk = 0; kk < 32; kk++) {
            float4 av = *(const float4*)&As[kk][ty*4];
            float4 b0 = *(const float4*)&Bs[kk][tx*8];
            float4 b1 = *(const float4*)&Bs[kk][tx*8 + 4];
            float a_[4] = {av.x, av.y, av.z, av.w};
            float b_[8] = {b0.x,b0.y,b0.z,b0.w, b1.x,b1.y,b1.z,b1.w};
#pragma unroll
            for (int ii = 0; ii < 4; ii++)
#pragma unroll
                for (int jj = 0; jj < 8; jj++) acc[ii][jj] += a_[ii] * b_[jj];
        }
        __syncthreads();
    }

#pragma unroll
    for (int im = 0; im < 4; im++) {
        int j = ty*4 + im;                    // 0..63 all valid (padded array)
        float* g = g_t + (size_t)(b * QS_ + j) * H_ + h0 + tx*8;
        *(float4*)(g)     = make_float4(acc[im][0], acc[im][1], acc[im][2], acc[im][3]);
        *(float4*)(g + 4) = make_float4(acc[im][4], acc[im][5], acc[im][6], acc[im][7]);
    }
}

// ============================================================
// K4: a = s1 @ qpad, bb = s1 @ t (K=64, two chunks of 32), fused epilogue:
//     out = [c, a, c*a, c*bb]. Tile 64(i) x 64(h). Micro 4x8, dual accumulators.
// ============================================================
__global__ __launch_bounds__(128) void k_out(
    const float* __restrict__ c, float* __restrict__ out)
{
    __shared__ __align__(16) float As[32][68];   // s1 transposed: As[j][m]
    __shared__ __align__(16) float Bq[32][68];   // qpad:          Bq[j][n]
    __shared__ __align__(16) float Bt[32][68];   // t:             Bt[j][n]

    int b  = blockIdx.z;
    int h0 = blockIdx.y * 64;
    int i0 = blockIdx.x * 64;
    int tid = threadIdx.x;
    int tx = tid & 7, ty = tid >> 3;

    float accA[4][8], accB[4][8];
#pragma unroll
    for (int i = 0; i < 4; i++)
#pragma unroll
        for (int j = 0; j < 8; j++) { accA[i][j] = 0.f; accB[i][j] = 0.f; }

    for (int jc = 0; jc < QS_; jc += 32) {
#pragma unroll
        for (int r = 0; r < 4; r++) {
            int p = tid + 128 * r;
            // A: s1 tile 64 m-rows x 32 j, transpose on store
            int m  = p >> 3;
            int j4 = (p & 7) * 4;
            float4 v = make_float4(0.f,0.f,0.f,0.f);
            int gi = i0 + m;
            if (gi < CL_) v = *(const float4*)(g_s1 + ((size_t)(b * CL_ + gi) << 6) + jc + j4);
            As[j4+0][m] = v.x; As[j4+1][m] = v.y; As[j4+2][m] = v.z; As[j4+3][m] = v.w;
            // B: qpad / t, 32 j-rows x 64 n, direct row copy
            int jj = p >> 4;
            int n4 = (p & 15) * 4;
            *(float4*)&Bq[jj][n4] = *(const float4*)(g_qpad + (size_t)(b*QS_ + jc + jj) * H_ + h0 + n4);
            *(float4*)&Bt[jj][n4] = *(const float4*)(g_t    + (size_t)(b*QS_ + jc + jj) * H_ + h0 + n4);
        }
        __syncthreads();

#pragma unroll
        for (int kk = 0; kk < 32; kk++) {
            float4 av = *(const float4*)&As[kk][ty*4];
            float4 q0 = *(const float4*)&Bq[kk][tx*8];
            float4 q1 = *(const float4*)&Bq[kk][tx*8 + 4];
            float4 t0 = *(const float4*)&Bt[kk][tx*8];
            float4 t1 = *(const float4*)&Bt[kk][tx*8 + 4];
            float a_[4] = {av.x, av.y, av.z, av.w};
            float q_[8] = {q0.x,q0.y,q0.z,q0.w, q1.x,q1.y,q1.z,q1.w};
            float t_[8] = {t0.x,t0.y,t0.z,t0.w, t1.x,t1.y,t1.z,t1.w};
#pragma unroll
            for (int ii = 0; ii < 4; ii++)
#pragma unroll
                for (int jj = 0; jj < 8; jj++) {
                    accA[ii][jj] += a_[ii] * q_[jj];
                    accB[ii][jj] += a_[ii] * t_[jj];
                }
        }
        __syncthreads();
    }

#pragma unroll
    for (int im = 0; im < 4; im++) {
        int gi = i0 + ty*4 + im;
        if (gi >= CL_) continue;
        const float* crow = c + (size_t)(b * CL_ + gi) * H_ + h0 + tx*8;
        float4 c0 = *(const float4*)(crow);
        float4 c1 = *(const float4*)(crow + 4);
        float4 a0 = make_float4(accA[im][0], accA[im][1], accA[im][2], accA[im][3]);
        float4 a1 = make_float4(accA[im][4], accA[im][5], accA[im][6], accA[im][7]);
        float4 b0 = make_float4(accB[im][0], accB[im][1], accB[im][2], accB[im][3]);
        float4 b1 = make_float4(accB[im][4], accB[im][5], accB[im][6], accB[im][7]);
        float* o = out + (size_t)(b * CL_ + gi) * (4 * H_) + h0 + tx*8;
        // section 0: c
        *(float4*)(o)            = c0;
        *(float4*)(o + 4)        = c1;
        // section 1: a
        *(float4*)(o + H_)       = a0;
        *(float4*)(o + H_ + 4)   = a1;
        // section 2: c*a
        *(float4*)(o + 2*H_)     = make_float4(c0.x*a0.x, c0.y*a0.y, c0.z*a0.z, c0.w*a0.w);
        *(float4*)(o + 2*H_ + 4) = make_float4(c1.x*a1.x, c1.y*a1.y, c1.z*a1.z, c1.w*a1.w);
        // section 3: c*b
        *(float4*)(o + 3*H_)     = make_float4(c0.x*b0.x, c0.y*b0.y, c0.z*b0.z, c0.w*b0.w);
        *(float4*)(o + 3*H_ + 4) = make_float4(c1.x*b1.x, c1.y*b1.y, c1.z*b1.z, c1.w*b1.w);
    }
}

// ============================================================
extern "C" void kernel_launch(void* const* d_in, const int* in_sizes, int n_in,
                              void* d_out, int out_size)
{
    const float* c    = (const float*)d_in[0];
    const float* q    = (const float*)d_in[1];
    const int*   cmask= (const int*)  d_in[2];
    const int*   qmask= (const int*)  d_in[3];
    const float* cw   = (const float*)d_in[4];
    const float* qw   = (const float*)d_in[5];
    const float* cqw  = (const float*)d_in[6];
    const float* bias = (const float*)d_in[7];
    float* out = (float*)d_out;

    k_dots   <<<3600, 256>>>(c, q, cw, qw);
    k_qpad   <<<4096, 256>>>(q);
    k_simgemm<<<dim3(7, B_), 128>>>(c, cqw);
    k_soft1  <<<3200, 256>>>(qmask, bias);
    k_soft2  <<<400, 256>>>(cmask, bias);
    k_s2tc   <<<dim3(16, B_), 128>>>(c);
    k_out    <<<dim3(7, 16, B_), 128>>>(c, out);
}